// round 1
// baseline (speedup 1.0000x reference)
#include <cuda_runtime.h>
#include <cuda_bf16.h>
#include <math.h>

// ---------------------------------------------------------------------------
// EncoderBlock: pre-LN transformer block, fp32 baseline (B=2, S=2048, D=1024,
// H=16, d_head=64, FF=4096).
// Pipeline:
//   h   = LN1(x)
//   q,k,v = h@W{q,k,v}+b
//   ctx = attention(q,k,v,mask)
//   x1  = x + ctx@Wo + bo
//   h   = LN2(x1)
//   ff  = relu(h@W1+b1)
//   out = x1 + ff@W2 + b2
// ---------------------------------------------------------------------------

#define D_MODEL 1024
#define N_HEADS 16
#define D_HEAD  64
#define FF_DIM  4096
#define BATCH   2
#define SEQ     2048
#define ROWS    (BATCH * SEQ)          // 4096
#define EPS     1e-5f

// ---- scratch (device globals; no allocation allowed) ----
__device__ float g_h  [ROWS * D_MODEL];
__device__ float g_q  [ROWS * D_MODEL];
__device__ float g_k  [ROWS * D_MODEL];
__device__ float g_v  [ROWS * D_MODEL];
__device__ float g_ctx[ROWS * D_MODEL];
__device__ float g_x1 [ROWS * D_MODEL];
__device__ float g_ff [ROWS * FF_DIM];

// ---------------------------------------------------------------------------
// Block-wide sum reduction (256 threads)
// ---------------------------------------------------------------------------
__device__ __forceinline__ float block_sum(float val, float* red) {
    #pragma unroll
    for (int o = 16; o > 0; o >>= 1)
        val += __shfl_xor_sync(0xffffffffu, val, o);
    int wid = threadIdx.x >> 5;
    if ((threadIdx.x & 31) == 0) red[wid] = val;
    __syncthreads();
    float t = (threadIdx.x < 8) ? red[threadIdx.x] : 0.0f;
    if (threadIdx.x < 32) {
        #pragma unroll
        for (int o = 16; o > 0; o >>= 1)
            t += __shfl_xor_sync(0xffffffffu, t, o);
        if (threadIdx.x == 0) red[0] = t;
    }
    __syncthreads();
    float r = red[0];
    __syncthreads();   // allow red[] reuse by a subsequent call
    return r;
}

// ---------------------------------------------------------------------------
// LayerNorm: one block (256 threads) per row of 1024
// ---------------------------------------------------------------------------
__global__ void ln_kernel(const float* __restrict__ X,
                          const float* __restrict__ gam,
                          const float* __restrict__ bet,
                          float* __restrict__ Y) {
    __shared__ float red[8];
    int row = blockIdx.x;
    const float* x = X + (size_t)row * D_MODEL;
    float v[4];
    float s = 0.0f;
    #pragma unroll
    for (int i = 0; i < 4; i++) {
        v[i] = x[threadIdx.x + i * 256];
        s += v[i];
    }
    float mu = block_sum(s, red) * (1.0f / D_MODEL);
    float ss = 0.0f;
    #pragma unroll
    for (int i = 0; i < 4; i++) {
        float d = v[i] - mu;
        ss += d * d;
    }
    float var = block_sum(ss, red) * (1.0f / D_MODEL);
    float rstd = rsqrtf(var + EPS);
    float* y = Y + (size_t)row * D_MODEL;
    #pragma unroll
    for (int i = 0; i < 4; i++) {
        int c = threadIdx.x + i * 256;
        y[c] = (v[i] - mu) * rstd * gam[c] + bet[c];
    }
}

// ---------------------------------------------------------------------------
// SGEMM: C[M,N] = A[M,K] @ B[K,N] + bias (+ residual) (+ relu)
// 64x64 tile, BK=16, 128 threads (16x8), 8x4 per-thread register block.
// M,N % 64 == 0 and K % 16 == 0 (all shapes here satisfy this).
// ---------------------------------------------------------------------------
template<bool RELU, bool RESID>
__global__ __launch_bounds__(128)
void sgemm64(const float* __restrict__ A, const float* __restrict__ Bm,
             const float* __restrict__ bias, const float* __restrict__ Rm,
             float* __restrict__ C, int M, int N, int K) {
    __shared__ float As[16][68];   // [kk][m], padded
    __shared__ float Bs[16][64];   // [kk][n]

    int tx = threadIdx.x;          // 0..15  (n)
    int ty = threadIdx.y;          // 0..7   (m)
    int tid = ty * 16 + tx;
    int m0 = blockIdx.y * 64;
    int n0 = blockIdx.x * 64;

    float acc[8][4];
    #pragma unroll
    for (int i = 0; i < 8; i++)
        #pragma unroll
        for (int j = 0; j < 4; j++)
            acc[i][j] = 0.0f;

    for (int k0 = 0; k0 < K; k0 += 16) {
        // A tile 64x16 -> As[kk][m]
        #pragma unroll
        for (int i = 0; i < 8; i++) {
            int e = tid + i * 128;       // 0..1023
            int m = e >> 4, kk = e & 15;
            As[kk][m] = A[(size_t)(m0 + m) * K + k0 + kk];
        }
        // B tile 16x64 -> Bs[kk][n] (float4)
        #pragma unroll
        for (int i = 0; i < 2; i++) {
            int e = tid + i * 128;       // 0..255 float4s
            int kk = e >> 4, n4 = e & 15;
            *(float4*)&Bs[kk][n4 * 4] =
                *(const float4*)&Bm[(size_t)(k0 + kk) * N + n0 + n4 * 4];
        }
        __syncthreads();

        #pragma unroll
        for (int kk = 0; kk < 16; kk++) {
            float a[8], b[4];
            #pragma unroll
            for (int i = 0; i < 8; i++) a[i] = As[kk][ty * 8 + i];
            #pragma unroll
            for (int j = 0; j < 4; j++) b[j] = Bs[kk][tx * 4 + j];
            #pragma unroll
            for (int i = 0; i < 8; i++)
                #pragma unroll
                for (int j = 0; j < 4; j++)
                    acc[i][j] = fmaf(a[i], b[j], acc[i][j]);
        }
        __syncthreads();
    }

    #pragma unroll
    for (int i = 0; i < 8; i++) {
        int m = m0 + ty * 8 + i;
        #pragma unroll
        for (int j = 0; j < 4; j++) {
            int n = n0 + tx * 4 + j;
            float vv = acc[i][j] + bias[n];
            if (RESID) vv += Rm[(size_t)m * N + n];
            if (RELU)  vv = fmaxf(vv, 0.0f);
            C[(size_t)m * N + n] = vv;
        }
    }
}

// ---------------------------------------------------------------------------
// Attention: flash-style. grid (S/64, H, B), 128 threads.
// Each thread pair owns one query row: thread = (r, half); half owns
// 32 output dims and 32 keys per tile; shfl_xor(1) merges pair state.
// Layout of q/k/v/ctx: [B*S, H*D_HEAD], head h at columns h*64..h*64+63.
// ---------------------------------------------------------------------------
__global__ __launch_bounds__(128)
void attn_kernel(const float* __restrict__ Q, const float* __restrict__ Kt,
                 const float* __restrict__ V, const int* __restrict__ mask,
                 float* __restrict__ O) {
    __shared__ float Ks[64][64];
    __shared__ float Vs[64][64];

    int qt = blockIdx.x, h = blockIdx.y, b = blockIdx.z;
    int tid = threadIdx.x;
    int r = tid >> 1, half = tid & 1;
    int qrow = qt * 64 + r;

    size_t qoff = ((size_t)(b * SEQ + qrow)) * D_MODEL + h * D_HEAD;
    float q[64];
    #pragma unroll
    for (int d = 0; d < 64; d += 4) {
        float4 t = *(const float4*)&Q[qoff + d];
        q[d] = t.x; q[d + 1] = t.y; q[d + 2] = t.z; q[d + 3] = t.w;
    }

    float acc[32];
    #pragma unroll
    for (int i = 0; i < 32; i++) acc[i] = 0.0f;
    float mrow = -INFINITY, lrow = 0.0f;
    const int* mrow_ptr = mask + b * SEQ;
    const int d0 = half * 32;

    for (int kt = 0; kt < SEQ / 64; kt++) {
        int key0 = kt * 64;
        // load K,V tiles (64x64 each), float4, cooperatively
        #pragma unroll
        for (int i = 0; i < 8; i++) {
            int e = tid + i * 128;        // 0..1023 float4 slots
            int kr = e >> 4, c4 = e & 15;
            size_t goff = ((size_t)(b * SEQ + key0 + kr)) * D_MODEL
                        + h * D_HEAD + c4 * 4;
            *(float4*)&Ks[kr][c4 * 4] = *(const float4*)&Kt[goff];
            *(float4*)&Vs[kr][c4 * 4] = *(const float4*)&V[goff];
        }
        __syncthreads();

        // scores for my 32 keys
        float sc[32];
        #pragma unroll
        for (int j = 0; j < 32; j++) {
            int kj = half * 32 + j;
            float dot = 0.0f;
            #pragma unroll
            for (int d = 0; d < 64; d++)
                dot = fmaf(q[d], Ks[kj][d], dot);
            dot *= 0.125f;                       // 1/sqrt(64)
            if (mrow_ptr[key0 + kj] == 0) dot = -INFINITY;
            sc[j] = dot;
        }

        float tmax = -INFINITY;
        #pragma unroll
        for (int j = 0; j < 32; j++) tmax = fmaxf(tmax, sc[j]);
        tmax = fmaxf(tmax, __shfl_xor_sync(0xffffffffu, tmax, 1));
        float mnew = fmaxf(mrow, tmax);

        float corr = (mnew == -INFINITY) ? 1.0f : __expf(mrow - mnew);
        float tsum = 0.0f;
        #pragma unroll
        for (int j = 0; j < 32; j++) {
            float p = (sc[j] == -INFINITY) ? 0.0f : __expf(sc[j] - mnew);
            sc[j] = p;
            tsum += p;
        }
        tsum += __shfl_xor_sync(0xffffffffu, tsum, 1);
        lrow = lrow * corr + tsum;
        mrow = mnew;
        #pragma unroll
        for (int i = 0; i < 32; i++) acc[i] *= corr;

        // accumulate O: my 32 dims over all 64 keys (partner's p via shfl)
        #pragma unroll
        for (int j = 0; j < 32; j++) {
            float pa = sc[j];
            float pb = __shfl_xor_sync(0xffffffffu, sc[j], 1);
            int ka = half * 32 + j;
            int kb = (half ^ 1) * 32 + j;
            #pragma unroll
            for (int dd = 0; dd < 32; dd++)
                acc[dd] = fmaf(pa, Vs[ka][d0 + dd],
                          fmaf(pb, Vs[kb][d0 + dd], acc[dd]));
        }
        __syncthreads();   // before next tile overwrites Ks/Vs
    }

    float inv = (lrow > 0.0f) ? (1.0f / lrow) : 0.0f;
    #pragma unroll
    for (int dd = 0; dd < 32; dd++)
        O[qoff + d0 + dd] = acc[dd] * inv;
}

// ---------------------------------------------------------------------------
// Launch
// ---------------------------------------------------------------------------
extern "C" void kernel_launch(void* const* d_in, const int* in_sizes, int n_in,
                              void* d_out, int out_size) {
    const float* x     = (const float*)d_in[0];
    const int*   mask  = (const int*)  d_in[1];
    const float* wq    = (const float*)d_in[2];
    const float* bq    = (const float*)d_in[3];
    const float* wk    = (const float*)d_in[4];
    const float* bk    = (const float*)d_in[5];
    const float* wv    = (const float*)d_in[6];
    const float* bv    = (const float*)d_in[7];
    const float* wo    = (const float*)d_in[8];
    const float* bo    = (const float*)d_in[9];
    const float* ln1g  = (const float*)d_in[10];
    const float* ln1b  = (const float*)d_in[11];
    const float* ln2g  = (const float*)d_in[12];
    const float* ln2b  = (const float*)d_in[13];
    const float* w1    = (const float*)d_in[14];
    const float* b1    = (const float*)d_in[15];
    const float* w2    = (const float*)d_in[16];
    const float* b2    = (const float*)d_in[17];
    float* out = (float*)d_out;

    float *h, *q, *k, *v, *ctx, *x1, *ff;
    cudaGetSymbolAddress((void**)&h,   g_h);
    cudaGetSymbolAddress((void**)&q,   g_q);
    cudaGetSymbolAddress((void**)&k,   g_k);
    cudaGetSymbolAddress((void**)&v,   g_v);
    cudaGetSymbolAddress((void**)&ctx, g_ctx);
    cudaGetSymbolAddress((void**)&x1,  g_x1);
    cudaGetSymbolAddress((void**)&ff,  g_ff);

    dim3 gblk(16, 8);

    // LN1
    ln_kernel<<<ROWS, 256>>>(x, ln1g, ln1b, h);
    // QKV projections
    sgemm64<false, false><<<dim3(D_MODEL / 64, ROWS / 64), gblk>>>(
        h, wq, bq, nullptr, q, ROWS, D_MODEL, D_MODEL);
    sgemm64<false, false><<<dim3(D_MODEL / 64, ROWS / 64), gblk>>>(
        h, wk, bk, nullptr, k, ROWS, D_MODEL, D_MODEL);
    sgemm64<false, false><<<dim3(D_MODEL / 64, ROWS / 64), gblk>>>(
        h, wv, bv, nullptr, v, ROWS, D_MODEL, D_MODEL);
    // attention
    attn_kernel<<<dim3(SEQ / 64, N_HEADS, BATCH), 128>>>(q, k, v, mask, ctx);
    // output projection + residual
    sgemm64<false, true><<<dim3(D_MODEL / 64, ROWS / 64), gblk>>>(
        ctx, wo, bo, x, x1, ROWS, D_MODEL, D_MODEL);
    // LN2
    ln_kernel<<<ROWS, 256>>>(x1, ln2g, ln2b, h);
    // FF1 (relu)
    sgemm64<true, false><<<dim3(FF_DIM / 64, ROWS / 64), gblk>>>(
        h, w1, b1, nullptr, ff, ROWS, FF_DIM, D_MODEL);
    // FF2 + residual -> out
    sgemm64<false, true><<<dim3(D_MODEL / 64, ROWS / 64), gblk>>>(
        ff, w2, b2, x1, out, ROWS, D_MODEL, FF_DIM);
}

// round 5
// speedup vs baseline: 1.5223x; 1.5223x over previous
#include <cuda_runtime.h>
#include <cuda_bf16.h>
#include <math.h>
#include <stdint.h>

// ---------------------------------------------------------------------------
// EncoderBlock fp32. GEMMs via mma.sync m16n8k8 tf32 (sm_80+ base ISA --
// tcgen05 unavailable: harness compiles for sm_100, not sm_100a).
// All GEMM operands pre-rounded to tf32 (rna) at producers so in-MMA
// truncation is exact. B=2, S=2048, D=1024, H=16, d_head=64, FF=4096.
// ---------------------------------------------------------------------------

#define D_MODEL 1024
#define N_HEADS 16
#define D_HEAD  64
#define FF_DIM  4096
#define BATCH   2
#define SEQ     2048
#define ROWS    (BATCH * SEQ)          // 4096
#define QKV_LD  (3 * D_MODEL)          // 3072
#define EPS     1e-5f

// ---- scratch (device globals; no allocation allowed) ----
__device__ float g_h   [ROWS * D_MODEL];
__device__ float g_qkv [(size_t)ROWS * QKV_LD];
__device__ float g_ctx [ROWS * D_MODEL];
__device__ float g_x1  [ROWS * D_MODEL];
__device__ float g_ff  [(size_t)ROWS * FF_DIM];
// transposed ([N,K], K-major) + tf32-rounded weights
__device__ float g_wqkvT[(size_t)QKV_LD * D_MODEL];
__device__ float g_woT  [D_MODEL * D_MODEL];
__device__ float g_w1T  [(size_t)FF_DIM * D_MODEL];
__device__ float g_w2T  [(size_t)D_MODEL * FF_DIM];
__device__ float g_bqkv [QKV_LD];

// ===========================================================================
// helpers
// ===========================================================================
__device__ __forceinline__ float f2tf32f(float f) {
    uint32_t u;
    asm("cvt.rna.tf32.f32 %0, %1;" : "=r"(u) : "f"(f));
    return __uint_as_float(u);
}
__device__ __forceinline__ uint32_t smem_u32(const void* p) {
    uint32_t a;
    asm("{ .reg .u64 t; cvta.to.shared.u64 t, %1; cvt.u32.u64 %0, t; }"
        : "=r"(a) : "l"(p));
    return a;
}
__device__ __forceinline__ void cp_async16(uint32_t dst, const void* src) {
    asm volatile("cp.async.ca.shared.global [%0], [%1], 16;"
                 :: "r"(dst), "l"(src));
}
#define CP_COMMIT() asm volatile("cp.async.commit_group;" ::: "memory")
#define CP_WAIT1()  asm volatile("cp.async.wait_group 1;" ::: "memory")
#define CP_WAIT0()  asm volatile("cp.async.wait_group 0;" ::: "memory")

__device__ __forceinline__ void mma_tf32(float* d, const uint32_t* a,
                                         uint32_t b0, uint32_t b1) {
    asm volatile(
        "mma.sync.aligned.m16n8k8.row.col.f32.tf32.tf32.f32 "
        "{%0,%1,%2,%3}, {%4,%5,%6,%7}, {%8,%9}, {%0,%1,%2,%3};\n"
        : "+f"(d[0]), "+f"(d[1]), "+f"(d[2]), "+f"(d[3])
        : "r"(a[0]), "r"(a[1]), "r"(a[2]), "r"(a[3]), "r"(b0), "r"(b1));
}

// ===========================================================================
// Weight transpose + tf32 rounding: out[C,R] = tf32(in[R,C]^T)
// Block (32,8), grid (C/32, R/32). 'out' may point into a packed buffer.
// ===========================================================================
__global__ void transpose_k(const float* __restrict__ in, float* __restrict__ out,
                            int R, int C) {
    __shared__ float t[32][33];
    int bx = blockIdx.x * 32, by = blockIdx.y * 32;
    int tx = threadIdx.x, ty = threadIdx.y;
    #pragma unroll
    for (int i = 0; i < 32; i += 8)
        t[ty + i][tx] = in[(size_t)(by + ty + i) * C + bx + tx];
    __syncthreads();
    #pragma unroll
    for (int i = 0; i < 32; i += 8)
        out[(size_t)(bx + ty + i) * R + by + tx] = f2tf32f(t[tx][ty + i]);
}

__global__ void concat_bias(const float* __restrict__ bq,
                            const float* __restrict__ bk,
                            const float* __restrict__ bv,
                            float* __restrict__ out) {
    int i = blockIdx.x * 256 + threadIdx.x;
    if (i >= QKV_LD) return;
    float v = (i < D_MODEL) ? bq[i]
            : (i < 2 * D_MODEL) ? bk[i - D_MODEL] : bv[i - 2 * D_MODEL];
    out[i] = v;
}

// ===========================================================================
// LayerNorm (writes tf32-rounded output; consumed only as GEMM A-operand)
// ===========================================================================
__device__ __forceinline__ float block_sum(float val, float* red) {
    #pragma unroll
    for (int o = 16; o > 0; o >>= 1)
        val += __shfl_xor_sync(0xffffffffu, val, o);
    int wid = threadIdx.x >> 5;
    if ((threadIdx.x & 31) == 0) red[wid] = val;
    __syncthreads();
    float t = (threadIdx.x < 8) ? red[threadIdx.x] : 0.0f;
    if (threadIdx.x < 32) {
        #pragma unroll
        for (int o = 16; o > 0; o >>= 1)
            t += __shfl_xor_sync(0xffffffffu, t, o);
        if (threadIdx.x == 0) red[0] = t;
    }
    __syncthreads();
    float r = red[0];
    __syncthreads();
    return r;
}

__global__ void ln_kernel(const float* __restrict__ X,
                          const float* __restrict__ gam,
                          const float* __restrict__ bet,
                          float* __restrict__ Y) {
    __shared__ float red[8];
    int row = blockIdx.x;
    const float* x = X + (size_t)row * D_MODEL;
    float v[4];
    float s = 0.0f;
    #pragma unroll
    for (int i = 0; i < 4; i++) {
        v[i] = x[threadIdx.x + i * 256];
        s += v[i];
    }
    float mu = block_sum(s, red) * (1.0f / D_MODEL);
    float ss = 0.0f;
    #pragma unroll
    for (int i = 0; i < 4; i++) {
        float d = v[i] - mu;
        ss += d * d;
    }
    float var = block_sum(ss, red) * (1.0f / D_MODEL);
    float rstd = rsqrtf(var + EPS);
    float* y = Y + (size_t)row * D_MODEL;
    #pragma unroll
    for (int i = 0; i < 4; i++) {
        int c = threadIdx.x + i * 256;
        y[c] = f2tf32f((v[i] - mu) * rstd * gam[c] + bet[c]);
    }
}

// ===========================================================================
// mma.sync tf32 GEMM: C[M,N] = A[M,K] @ Bt[N,K]^T + bias (+resid)(+relu)(round)
// CTA 128x128x32, 256 threads, 8 warps (4m x 2n), warp tile 32x64.
// Smem rows padded to 36 floats: fragment bank = (4g+tg)%32, conflict-free.
// A and Bt must be pre-rounded to tf32 (mma truncation then exact).
// ===========================================================================
#define GM_STAGE_F  (2 * 128 * 36)          // floats per stage (A+B)
#define GM_SMEM_B   (2 * GM_STAGE_F * 4)    // 73728 bytes

template<bool RELU, bool RESID, bool ROUND>
__global__ __launch_bounds__(256)
void mmagemm(const float* __restrict__ A, const float* __restrict__ Bt,
             const float* __restrict__ bias, const float* __restrict__ Rm,
             float* __restrict__ C, int M, int N, int K) {
    extern __shared__ float smem[];
    float* As[2] = { smem,                 smem + GM_STAGE_F };
    float* Bs[2] = { smem + 128 * 36,      smem + GM_STAGE_F + 128 * 36 };

    int tid = threadIdx.x;
    int w = tid >> 5, lane = tid & 31;
    int wm = w & 3, wn = w >> 2;           // 4 m-warps x 2 n-warps
    int g = lane >> 2, tg = lane & 3;
    int m0 = blockIdx.y * 128, n0 = blockIdx.x * 128;

    float acc[2][8][4];
    #pragma unroll
    for (int mt = 0; mt < 2; mt++)
        #pragma unroll
        for (int nt = 0; nt < 8; nt++)
            #pragma unroll
            for (int i = 0; i < 4; i++)
                acc[mt][nt][i] = 0.0f;

    uint32_t sA[2] = { smem_u32(As[0]), smem_u32(As[1]) };
    uint32_t sB[2] = { smem_u32(Bs[0]), smem_u32(Bs[1]) };

    auto load_stage = [&](int st, int k0) {
        #pragma unroll
        for (int i = 0; i < 4; i++) {
            int c = tid + i * 256;          // 0..1023 float4 chunks
            int r = c >> 3, c8 = c & 7;
            cp_async16(sA[st] + (uint32_t)(r * 36 + c8 * 4) * 4,
                       A + (size_t)(m0 + r) * K + k0 + c8 * 4);
        }
        #pragma unroll
        for (int i = 0; i < 4; i++) {
            int c = tid + i * 256;
            int r = c >> 3, c8 = c & 7;
            cp_async16(sB[st] + (uint32_t)(r * 36 + c8 * 4) * 4,
                       Bt + (size_t)(n0 + r) * K + k0 + c8 * 4);
        }
        CP_COMMIT();
    };

    load_stage(0, 0);
    const int KT = K >> 5;
    for (int kt = 0; kt < KT; kt++) {
        int st = kt & 1;
        if (kt + 1 < KT) { load_stage(st ^ 1, (kt + 1) * 32); CP_WAIT1(); }
        else             { CP_WAIT0(); }
        __syncthreads();

        const float* As_ = As[st];
        const float* Bs_ = Bs[st];
        #pragma unroll
        for (int ks = 0; ks < 4; ks++) {
            int kk = ks * 8 + tg;
            uint32_t af[2][4];
            #pragma unroll
            for (int mt = 0; mt < 2; mt++) {
                int r = wm * 32 + mt * 16 + g;
                af[mt][0] = __float_as_uint(As_[r * 36 + kk]);
                af[mt][1] = __float_as_uint(As_[(r + 8) * 36 + kk]);
                af[mt][2] = __float_as_uint(As_[r * 36 + kk + 4]);
                af[mt][3] = __float_as_uint(As_[(r + 8) * 36 + kk + 4]);
            }
            #pragma unroll
            for (int nt = 0; nt < 8; nt++) {
                int n = wn * 64 + nt * 8 + g;
                uint32_t b0 = __float_as_uint(Bs_[n * 36 + kk]);
                uint32_t b1 = __float_as_uint(Bs_[n * 36 + kk + 4]);
                #pragma unroll
                for (int mt = 0; mt < 2; mt++)
                    mma_tf32(acc[mt][nt], af[mt], b0, b1);
            }
        }
        __syncthreads();
    }

    // epilogue: c0,c1 at (r, col..col+1); c2,c3 at (r+8, col..col+1)
    #pragma unroll
    for (int mt = 0; mt < 2; mt++) {
        int r = m0 + wm * 32 + mt * 16 + g;
        #pragma unroll
        for (int nt = 0; nt < 8; nt++) {
            int col = n0 + wn * 64 + nt * 8 + tg * 2;
            float bx_ = bias[col], by_ = bias[col + 1];
            float* d = acc[mt][nt];
            float2 lo = { d[0] + bx_, d[1] + by_ };
            float2 hi = { d[2] + bx_, d[3] + by_ };
            if (RESID) {
                float2 r0 = *(const float2*)&Rm[(size_t)r * N + col];
                float2 r1 = *(const float2*)&Rm[(size_t)(r + 8) * N + col];
                lo.x += r0.x; lo.y += r0.y; hi.x += r1.x; hi.y += r1.y;
            }
            if (RELU) {
                lo.x = fmaxf(lo.x, 0.0f); lo.y = fmaxf(lo.y, 0.0f);
                hi.x = fmaxf(hi.x, 0.0f); hi.y = fmaxf(hi.y, 0.0f);
            }
            if (ROUND) {
                lo.x = f2tf32f(lo.x); lo.y = f2tf32f(lo.y);
                hi.x = f2tf32f(hi.x); hi.y = f2tf32f(hi.y);
            }
            *(float2*)&C[(size_t)r * N + col]       = lo;
            *(float2*)&C[(size_t)(r + 8) * N + col] = hi;
        }
    }
}

// ===========================================================================
// Attention: flash-style fp32 over fused qkv buffer (row stride 3072).
// Output ctx tf32-rounded (feeds Wo GEMM A-operand).
// ===========================================================================
__global__ __launch_bounds__(128)
void attn_kernel(const float* __restrict__ QKV, const int* __restrict__ mask,
                 float* __restrict__ O) {
    __shared__ float Ks[64][64];
    __shared__ float Vs[64][64];

    int qt = blockIdx.x, h = blockIdx.y, b = blockIdx.z;
    int tid = threadIdx.x;
    int r = tid >> 1, half = tid & 1;
    int qrow = qt * 64 + r;

    size_t qoff = ((size_t)(b * SEQ + qrow)) * QKV_LD + h * D_HEAD;
    float q[64];
    #pragma unroll
    for (int d = 0; d < 64; d += 4) {
        float4 t = *(const float4*)&QKV[qoff + d];
        q[d] = t.x; q[d + 1] = t.y; q[d + 2] = t.z; q[d + 3] = t.w;
    }

    float acc[32];
    #pragma unroll
    for (int i = 0; i < 32; i++) acc[i] = 0.0f;
    float mrow = -INFINITY, lrow = 0.0f;
    const int* mrow_ptr = mask + b * SEQ;
    const int d0 = half * 32;

    for (int kt = 0; kt < SEQ / 64; kt++) {
        int key0 = kt * 64;
        #pragma unroll
        for (int i = 0; i < 8; i++) {
            int e = tid + i * 128;
            int kr = e >> 4, c4 = e & 15;
            size_t goff = ((size_t)(b * SEQ + key0 + kr)) * QKV_LD
                        + h * D_HEAD + c4 * 4;
            *(float4*)&Ks[kr][c4 * 4] = *(const float4*)&QKV[goff + D_MODEL];
            *(float4*)&Vs[kr][c4 * 4] = *(const float4*)&QKV[goff + 2 * D_MODEL];
        }
        __syncthreads();

        float sc[32];
        #pragma unroll
        for (int j = 0; j < 32; j++) {
            int kj = half * 32 + j;
            float dot = 0.0f;
            #pragma unroll
            for (int d = 0; d < 64; d++)
                dot = fmaf(q[d], Ks[kj][d], dot);
            dot *= 0.125f;
            if (mrow_ptr[key0 + kj] == 0) dot = -INFINITY;
            sc[j] = dot;
        }

        float tmax = -INFINITY;
        #pragma unroll
        for (int j = 0; j < 32; j++) tmax = fmaxf(tmax, sc[j]);
        tmax = fmaxf(tmax, __shfl_xor_sync(0xffffffffu, tmax, 1));
        float mnew = fmaxf(mrow, tmax);

        float corr = (mnew == -INFINITY) ? 1.0f : __expf(mrow - mnew);
        float tsum = 0.0f;
        #pragma unroll
        for (int j = 0; j < 32; j++) {
            float p = (sc[j] == -INFINITY) ? 0.0f : __expf(sc[j] - mnew);
            sc[j] = p;
            tsum += p;
        }
        tsum += __shfl_xor_sync(0xffffffffu, tsum, 1);
        lrow = lrow * corr + tsum;
        mrow = mnew;
        #pragma unroll
        for (int i = 0; i < 32; i++) acc[i] *= corr;

        #pragma unroll
        for (int j = 0; j < 32; j++) {
            float pa = sc[j];
            float pb = __shfl_xor_sync(0xffffffffu, sc[j], 1);
            int ka = half * 32 + j;
            int kb = (half ^ 1) * 32 + j;
            #pragma unroll
            for (int dd = 0; dd < 32; dd++)
                acc[dd] = fmaf(pa, Vs[ka][d0 + dd],
                          fmaf(pb, Vs[kb][d0 + dd], acc[dd]));
        }
        __syncthreads();
    }

    float inv = (lrow > 0.0f) ? (1.0f / lrow) : 0.0f;
    size_t ooff = ((size_t)(b * SEQ + qrow)) * D_MODEL + h * D_HEAD + d0;
    #pragma unroll
    for (int dd = 0; dd < 32; dd++)
        O[ooff + dd] = f2tf32f(acc[dd] * inv);
}

// ===========================================================================
// Launch
// ===========================================================================
extern "C" void kernel_launch(void* const* d_in, const int* in_sizes, int n_in,
                              void* d_out, int out_size) {
    const float* x     = (const float*)d_in[0];
    const int*   mask  = (const int*)  d_in[1];
    const float* wq    = (const float*)d_in[2];
    const float* bq    = (const float*)d_in[3];
    const float* wk    = (const float*)d_in[4];
    const float* bk    = (const float*)d_in[5];
    const float* wv    = (const float*)d_in[6];
    const float* bv    = (const float*)d_in[7];
    const float* wo    = (const float*)d_in[8];
    const float* bo    = (const float*)d_in[9];
    const float* ln1g  = (const float*)d_in[10];
    const float* ln1b  = (const float*)d_in[11];
    const float* ln2g  = (const float*)d_in[12];
    const float* ln2b  = (const float*)d_in[13];
    const float* w1    = (const float*)d_in[14];
    const float* b1    = (const float*)d_in[15];
    const float* w2    = (const float*)d_in[16];
    const float* b2    = (const float*)d_in[17];
    float* out = (float*)d_out;

    float *h, *qkv, *ctx, *x1, *ff;
    float *wqkvT, *woT, *w1T, *w2T, *bqkv;
    cudaGetSymbolAddress((void**)&h,     g_h);
    cudaGetSymbolAddress((void**)&qkv,   g_qkv);
    cudaGetSymbolAddress((void**)&ctx,   g_ctx);
    cudaGetSymbolAddress((void**)&x1,    g_x1);
    cudaGetSymbolAddress((void**)&ff,    g_ff);
    cudaGetSymbolAddress((void**)&wqkvT, g_wqkvT);
    cudaGetSymbolAddress((void**)&woT,   g_woT);
    cudaGetSymbolAddress((void**)&w1T,   g_w1T);
    cudaGetSymbolAddress((void**)&w2T,   g_w2T);
    cudaGetSymbolAddress((void**)&bqkv,  g_bqkv);

    cudaFuncSetAttribute(mmagemm<false, false, false>,
        cudaFuncAttributeMaxDynamicSharedMemorySize, GM_SMEM_B);
    cudaFuncSetAttribute(mmagemm<true, false, true>,
        cudaFuncAttributeMaxDynamicSharedMemorySize, GM_SMEM_B);
    cudaFuncSetAttribute(mmagemm<false, true, false>,
        cudaFuncAttributeMaxDynamicSharedMemorySize, GM_SMEM_B);

    dim3 tblk(32, 8);
    // weight transposes + tf32 rounding; wq/wk/wv packed into wqkvT
    transpose_k<<<dim3(32, 32), tblk>>>(wq, wqkvT,                       D_MODEL, D_MODEL);
    transpose_k<<<dim3(32, 32), tblk>>>(wk, wqkvT + D_MODEL * D_MODEL,   D_MODEL, D_MODEL);
    transpose_k<<<dim3(32, 32), tblk>>>(wv, wqkvT + 2 * D_MODEL * D_MODEL, D_MODEL, D_MODEL);
    transpose_k<<<dim3(32, 32), tblk>>>(wo, woT, D_MODEL, D_MODEL);
    transpose_k<<<dim3(FF_DIM / 32, 32), tblk>>>(w1, w1T, D_MODEL, FF_DIM);
    transpose_k<<<dim3(32, FF_DIM / 32), tblk>>>(w2, w2T, FF_DIM, D_MODEL);
    concat_bias<<<QKV_LD / 256, 256>>>(bq, bk, bv, bqkv);

    // LN1 (tf32-rounded output)
    ln_kernel<<<ROWS, 256>>>(x, ln1g, ln1b, h);
    // fused QKV projection: [4096,1024] @ [1024,3072]
    mmagemm<false, false, false><<<dim3(QKV_LD / 128, ROWS / 128), 256, GM_SMEM_B>>>(
        h, wqkvT, bqkv, nullptr, qkv, ROWS, QKV_LD, D_MODEL);
    // attention (ctx tf32-rounded)
    attn_kernel<<<dim3(SEQ / 64, N_HEADS, BATCH), 128>>>(qkv, mask, ctx);
    // output projection + residual
    mmagemm<false, true, false><<<dim3(D_MODEL / 128, ROWS / 128), 256, GM_SMEM_B>>>(
        ctx, woT, bo, x, x1, ROWS, D_MODEL, D_MODEL);
    // LN2 (tf32-rounded output)
    ln_kernel<<<ROWS, 256>>>(x1, ln2g, ln2b, h);
    // FF1: relu + tf32 round (feeds FF2 A-operand)
    mmagemm<true, false, true><<<dim3(FF_DIM / 128, ROWS / 128), 256, GM_SMEM_B>>>(
        h, w1T, b1, nullptr, ff, ROWS, FF_DIM, D_MODEL);
    // FF2 + residual -> out
    mmagemm<false, true, false><<<dim3(D_MODEL / 128, ROWS / 128), 256, GM_SMEM_B>>>(
        ff, w2T, b2, x1, out, ROWS, D_MODEL, FF_DIM);
}

// round 6
// speedup vs baseline: 3.2414x; 2.1293x over previous
#include <cuda_runtime.h>
#include <cuda_bf16.h>
#include <math.h>
#include <stdint.h>

// ---------------------------------------------------------------------------
// EncoderBlock fp32. GEMMs + attention via mma.sync m16n8k8 tf32.
// All GEMM operands pre-rounded to tf32 (rna) at producers.
// B=2, S=2048, D=1024, H=16, d_head=64, FF=4096.
// ---------------------------------------------------------------------------

#define D_MODEL 1024
#define N_HEADS 16
#define D_HEAD  64
#define FF_DIM  4096
#define BATCH   2
#define SEQ     2048
#define ROWS    (BATCH * SEQ)          // 4096
#define QKV_LD  (3 * D_MODEL)          // 3072
#define EPS     1e-5f

// ---- scratch (device globals; no allocation allowed) ----
__device__ float g_h   [ROWS * D_MODEL];
__device__ float g_qkv [(size_t)ROWS * QKV_LD];
__device__ float g_ctx [ROWS * D_MODEL];
__device__ float g_x1  [ROWS * D_MODEL];
__device__ float g_ff  [(size_t)ROWS * FF_DIM];
__device__ float g_wqkvT[(size_t)QKV_LD * D_MODEL];
__device__ float g_woT  [D_MODEL * D_MODEL];
__device__ float g_w1T  [(size_t)FF_DIM * D_MODEL];
__device__ float g_w2T  [(size_t)D_MODEL * FF_DIM];
__device__ float g_bqkv [QKV_LD];

// ===========================================================================
// helpers
// ===========================================================================
__device__ __forceinline__ float f2tf32f(float f) {
    uint32_t u;
    asm("cvt.rna.tf32.f32 %0, %1;" : "=r"(u) : "f"(f));
    return __uint_as_float(u);
}
__device__ __forceinline__ uint32_t smem_u32(const void* p) {
    uint32_t a;
    asm("{ .reg .u64 t; cvta.to.shared.u64 t, %1; cvt.u32.u64 %0, t; }"
        : "=r"(a) : "l"(p));
    return a;
}
__device__ __forceinline__ void cp_async16(uint32_t dst, const void* src) {
    asm volatile("cp.async.ca.shared.global [%0], [%1], 16;"
                 :: "r"(dst), "l"(src));
}
#define CP_COMMIT() asm volatile("cp.async.commit_group;" ::: "memory")
#define CP_WAIT1()  asm volatile("cp.async.wait_group 1;" ::: "memory")
#define CP_WAIT0()  asm volatile("cp.async.wait_group 0;" ::: "memory")

__device__ __forceinline__ void mma_tf32(float* d, const uint32_t* a,
                                         uint32_t b0, uint32_t b1) {
    asm volatile(
        "mma.sync.aligned.m16n8k8.row.col.f32.tf32.tf32.f32 "
        "{%0,%1,%2,%3}, {%4,%5,%6,%7}, {%8,%9}, {%0,%1,%2,%3};\n"
        : "+f"(d[0]), "+f"(d[1]), "+f"(d[2]), "+f"(d[3])
        : "r"(a[0]), "r"(a[1]), "r"(a[2]), "r"(a[3]), "r"(b0), "r"(b1));
}

// ===========================================================================
// Weight transpose + tf32 rounding
// ===========================================================================
__global__ void transpose_k(const float* __restrict__ in, float* __restrict__ out,
                            int R, int C) {
    __shared__ float t[32][33];
    int bx = blockIdx.x * 32, by = blockIdx.y * 32;
    int tx = threadIdx.x, ty = threadIdx.y;
    #pragma unroll
    for (int i = 0; i < 32; i += 8)
        t[ty + i][tx] = in[(size_t)(by + ty + i) * C + bx + tx];
    __syncthreads();
    #pragma unroll
    for (int i = 0; i < 32; i += 8)
        out[(size_t)(bx + ty + i) * R + by + tx] = f2tf32f(t[tx][ty + i]);
}

__global__ void concat_bias(const float* __restrict__ bq,
                            const float* __restrict__ bk,
                            const float* __restrict__ bv,
                            float* __restrict__ out) {
    int i = blockIdx.x * 256 + threadIdx.x;
    if (i >= QKV_LD) return;
    float v = (i < D_MODEL) ? bq[i]
            : (i < 2 * D_MODEL) ? bk[i - D_MODEL] : bv[i - 2 * D_MODEL];
    out[i] = v;
}

// ===========================================================================
// LayerNorm (tf32-rounded output; consumed only as GEMM A-operand)
// ===========================================================================
__device__ __forceinline__ float block_sum(float val, float* red) {
    #pragma unroll
    for (int o = 16; o > 0; o >>= 1)
        val += __shfl_xor_sync(0xffffffffu, val, o);
    int wid = threadIdx.x >> 5;
    if ((threadIdx.x & 31) == 0) red[wid] = val;
    __syncthreads();
    float t = (threadIdx.x < 8) ? red[threadIdx.x] : 0.0f;
    if (threadIdx.x < 32) {
        #pragma unroll
        for (int o = 16; o > 0; o >>= 1)
            t += __shfl_xor_sync(0xffffffffu, t, o);
        if (threadIdx.x == 0) red[0] = t;
    }
    __syncthreads();
    float r = red[0];
    __syncthreads();
    return r;
}

__global__ void ln_kernel(const float* __restrict__ X,
                          const float* __restrict__ gam,
                          const float* __restrict__ bet,
                          float* __restrict__ Y) {
    __shared__ float red[8];
    int row = blockIdx.x;
    const float* x = X + (size_t)row * D_MODEL;
    float v[4];
    float s = 0.0f;
    #pragma unroll
    for (int i = 0; i < 4; i++) {
        v[i] = x[threadIdx.x + i * 256];
        s += v[i];
    }
    float mu = block_sum(s, red) * (1.0f / D_MODEL);
    float ss = 0.0f;
    #pragma unroll
    for (int i = 0; i < 4; i++) {
        float d = v[i] - mu;
        ss += d * d;
    }
    float var = block_sum(ss, red) * (1.0f / D_MODEL);
    float rstd = rsqrtf(var + EPS);
    float* y = Y + (size_t)row * D_MODEL;
    #pragma unroll
    for (int i = 0; i < 4; i++) {
        int c = threadIdx.x + i * 256;
        y[c] = f2tf32f((v[i] - mu) * rstd * gam[c] + bet[c]);
    }
}

// ===========================================================================
// mma.sync tf32 GEMM (unchanged from R5 passing version)
// ===========================================================================
#define GM_STAGE_F  (2 * 128 * 36)
#define GM_SMEM_B   (2 * GM_STAGE_F * 4)

template<bool RELU, bool RESID, bool ROUND>
__global__ __launch_bounds__(256)
void mmagemm(const float* __restrict__ A, const float* __restrict__ Bt,
             const float* __restrict__ bias, const float* __restrict__ Rm,
             float* __restrict__ C, int M, int N, int K) {
    extern __shared__ float smem[];
    float* As[2] = { smem,                 smem + GM_STAGE_F };
    float* Bs[2] = { smem + 128 * 36,      smem + GM_STAGE_F + 128 * 36 };

    int tid = threadIdx.x;
    int w = tid >> 5, lane = tid & 31;
    int wm = w & 3, wn = w >> 2;
    int g = lane >> 2, tg = lane & 3;
    int m0 = blockIdx.y * 128, n0 = blockIdx.x * 128;

    float acc[2][8][4];
    #pragma unroll
    for (int mt = 0; mt < 2; mt++)
        #pragma unroll
        for (int nt = 0; nt < 8; nt++)
            #pragma unroll
            for (int i = 0; i < 4; i++)
                acc[mt][nt][i] = 0.0f;

    uint32_t sA[2] = { smem_u32(As[0]), smem_u32(As[1]) };
    uint32_t sB[2] = { smem_u32(Bs[0]), smem_u32(Bs[1]) };

    auto load_stage = [&](int st, int k0) {
        #pragma unroll
        for (int i = 0; i < 4; i++) {
            int c = tid + i * 256;
            int r = c >> 3, c8 = c & 7;
            cp_async16(sA[st] + (uint32_t)(r * 36 + c8 * 4) * 4,
                       A + (size_t)(m0 + r) * K + k0 + c8 * 4);
        }
        #pragma unroll
        for (int i = 0; i < 4; i++) {
            int c = tid + i * 256;
            int r = c >> 3, c8 = c & 7;
            cp_async16(sB[st] + (uint32_t)(r * 36 + c8 * 4) * 4,
                       Bt + (size_t)(n0 + r) * K + k0 + c8 * 4);
        }
        CP_COMMIT();
    };

    load_stage(0, 0);
    const int KT = K >> 5;
    for (int kt = 0; kt < KT; kt++) {
        int st = kt & 1;
        if (kt + 1 < KT) { load_stage(st ^ 1, (kt + 1) * 32); CP_WAIT1(); }
        else             { CP_WAIT0(); }
        __syncthreads();

        const float* As_ = As[st];
        const float* Bs_ = Bs[st];
        #pragma unroll
        for (int ks = 0; ks < 4; ks++) {
            int kk = ks * 8 + tg;
            uint32_t af[2][4];
            #pragma unroll
            for (int mt = 0; mt < 2; mt++) {
                int r = wm * 32 + mt * 16 + g;
                af[mt][0] = __float_as_uint(As_[r * 36 + kk]);
                af[mt][1] = __float_as_uint(As_[(r + 8) * 36 + kk]);
                af[mt][2] = __float_as_uint(As_[r * 36 + kk + 4]);
                af[mt][3] = __float_as_uint(As_[(r + 8) * 36 + kk + 4]);
            }
            #pragma unroll
            for (int nt = 0; nt < 8; nt++) {
                int n = wn * 64 + nt * 8 + g;
                uint32_t b0 = __float_as_uint(Bs_[n * 36 + kk]);
                uint32_t b1 = __float_as_uint(Bs_[n * 36 + kk + 4]);
                #pragma unroll
                for (int mt = 0; mt < 2; mt++)
                    mma_tf32(acc[mt][nt], af[mt], b0, b1);
            }
        }
        __syncthreads();
    }

    #pragma unroll
    for (int mt = 0; mt < 2; mt++) {
        int r = m0 + wm * 32 + mt * 16 + g;
        #pragma unroll
        for (int nt = 0; nt < 8; nt++) {
            int col = n0 + wn * 64 + nt * 8 + tg * 2;
            float bx_ = bias[col], by_ = bias[col + 1];
            float* d = acc[mt][nt];
            float2 lo = { d[0] + bx_, d[1] + by_ };
            float2 hi = { d[2] + bx_, d[3] + by_ };
            if (RESID) {
                float2 r0 = *(const float2*)&Rm[(size_t)r * N + col];
                float2 r1 = *(const float2*)&Rm[(size_t)(r + 8) * N + col];
                lo.x += r0.x; lo.y += r0.y; hi.x += r1.x; hi.y += r1.y;
            }
            if (RELU) {
                lo.x = fmaxf(lo.x, 0.0f); lo.y = fmaxf(lo.y, 0.0f);
                hi.x = fmaxf(hi.x, 0.0f); hi.y = fmaxf(hi.y, 0.0f);
            }
            if (ROUND) {
                lo.x = f2tf32f(lo.x); lo.y = f2tf32f(lo.y);
                hi.x = f2tf32f(hi.x); hi.y = f2tf32f(hi.y);
            }
            *(float2*)&C[(size_t)r * N + col]       = lo;
            *(float2*)&C[(size_t)(r + 8) * N + col] = hi;
        }
    }
}

// ===========================================================================
// Attention via mma.sync tf32: flash-style, 128-query tile per CTA, 8 warps,
// each warp owns one m16 row-slab. K tile [key][dim] and V^T tile [dim][key]
// in smem (pad-68 rows: fragment bank (4g+tg)%32, conflict-free). P staged
// through warp-private smem rows to reshape accum->A-fragment for PV.
// Q fragments pre-scaled by 1/sqrt(d)=0.125 (exact).
// ===========================================================================
#define ATT_PAD   68
#define ATT_KS    0
#define ATT_VT    (64 * ATT_PAD)
#define ATT_PS    (2 * 64 * ATT_PAD)
#define ATT_BS    (2 * 64 * ATT_PAD + 128 * ATT_PAD)
#define ATT_SMEM_B ((ATT_BS + 64) * 4)

__global__ __launch_bounds__(256)
void attn_mma(const float* __restrict__ QKV, const int* __restrict__ mask,
              float* __restrict__ O) {
    extern __shared__ float sm[];
    float* Ks = sm + ATT_KS;
    float* Vt = sm + ATT_VT;
    float* Ps = sm + ATT_PS;
    float* bs = sm + ATT_BS;

    int tid = threadIdx.x, w = tid >> 5, lane = tid & 31;
    int g = lane >> 2, tg = lane & 3;
    int qt = blockIdx.x, h = blockIdx.y, b = blockIdx.z;
    int rloc = w * 16 + g;                       // CTA-local row of a0/c0

    const float* Qp = QKV + ((size_t)(b * SEQ + qt * 128 + rloc)) * QKV_LD
                    + h * D_HEAD;
    const float* Kbase = QKV + (size_t)b * SEQ * QKV_LD + D_MODEL + h * D_HEAD;
    const float* Vbase = Kbase + D_MODEL;
    const int* mp = mask + b * SEQ;

    // Q fragments (pre-scaled by 0.125)
    float qf[8][4];
    #pragma unroll
    for (int ks = 0; ks < 8; ks++) {
        int c = ks * 8 + tg;
        qf[ks][0] = Qp[c] * 0.125f;
        qf[ks][1] = Qp[(size_t)8 * QKV_LD + c] * 0.125f;
        qf[ks][2] = Qp[c + 4] * 0.125f;
        qf[ks][3] = Qp[(size_t)8 * QKV_LD + c + 4] * 0.125f;
    }

    float o[8][4];
    #pragma unroll
    for (int nt = 0; nt < 8; nt++)
        #pragma unroll
        for (int i = 0; i < 4; i++) o[nt][i] = 0.0f;
    float m0 = -INFINITY, m1 = -INFINITY, l0 = 0.0f, l1 = 0.0f;

    for (int kt = 0; kt < SEQ / 64; kt++) {
        int key0 = kt * 64;
        // ---- load K tile + transposed V tile ----
        #pragma unroll
        for (int i = 0; i < 4; i++) {
            int e = tid + i * 256;               // 0..1023 float4
            int row = e >> 4, c4 = e & 15;
            const float* kr = Kbase + (size_t)(key0 + row) * QKV_LD + c4 * 4;
            *(float4*)&Ks[row * ATT_PAD + c4 * 4] = *(const float4*)kr;
            float4 vv = *(const float4*)(Vbase + (size_t)(key0 + row) * QKV_LD + c4 * 4);
            Vt[(c4 * 4 + 0) * ATT_PAD + row] = vv.x;
            Vt[(c4 * 4 + 1) * ATT_PAD + row] = vv.y;
            Vt[(c4 * 4 + 2) * ATT_PAD + row] = vv.z;
            Vt[(c4 * 4 + 3) * ATT_PAD + row] = vv.w;
        }
        if (tid < 64)
            bs[tid] = (mp[key0 + tid] == 0) ? -INFINITY : 0.0f;
        __syncthreads();

        // ---- S = Q @ K^T (scaled) ----
        float s[8][4];
        #pragma unroll
        for (int nt = 0; nt < 8; nt++)
            #pragma unroll
            for (int i = 0; i < 4; i++) s[nt][i] = 0.0f;
        #pragma unroll
        for (int ks = 0; ks < 8; ks++) {
            int kk = ks * 8 + tg;
            uint32_t a[4] = { __float_as_uint(qf[ks][0]), __float_as_uint(qf[ks][1]),
                              __float_as_uint(qf[ks][2]), __float_as_uint(qf[ks][3]) };
            #pragma unroll
            for (int nt = 0; nt < 8; nt++) {
                int n = nt * 8 + g;
                uint32_t b0 = __float_as_uint(Ks[n * ATT_PAD + kk]);
                uint32_t b1 = __float_as_uint(Ks[n * ATT_PAD + kk + 4]);
                mma_tf32(s[nt], a, b0, b1);
            }
        }

        // ---- online softmax ----
        float tmax0 = -INFINITY, tmax1 = -INFINITY;
        #pragma unroll
        for (int nt = 0; nt < 8; nt++) {
            int c = nt * 8 + tg * 2;
            float b0 = bs[c], b1 = bs[c + 1];
            s[nt][0] += b0; s[nt][1] += b1;
            s[nt][2] += b0; s[nt][3] += b1;
            tmax0 = fmaxf(tmax0, fmaxf(s[nt][0], s[nt][1]));
            tmax1 = fmaxf(tmax1, fmaxf(s[nt][2], s[nt][3]));
        }
        tmax0 = fmaxf(tmax0, __shfl_xor_sync(0xffffffffu, tmax0, 1));
        tmax0 = fmaxf(tmax0, __shfl_xor_sync(0xffffffffu, tmax0, 2));
        tmax1 = fmaxf(tmax1, __shfl_xor_sync(0xffffffffu, tmax1, 1));
        tmax1 = fmaxf(tmax1, __shfl_xor_sync(0xffffffffu, tmax1, 2));
        float mn0 = fmaxf(m0, tmax0), mn1 = fmaxf(m1, tmax1);
        float c0 = (mn0 == -INFINITY) ? 1.0f : __expf(m0 - mn0);
        float c1 = (mn1 == -INFINITY) ? 1.0f : __expf(m1 - mn1);

        float rs0 = 0.0f, rs1 = 0.0f;
        #pragma unroll
        for (int nt = 0; nt < 8; nt++) {
            int c = nt * 8 + tg * 2;
            float p0 = (s[nt][0] == -INFINITY) ? 0.0f : __expf(s[nt][0] - mn0);
            float p1 = (s[nt][1] == -INFINITY) ? 0.0f : __expf(s[nt][1] - mn0);
            float p2 = (s[nt][2] == -INFINITY) ? 0.0f : __expf(s[nt][2] - mn1);
            float p3 = (s[nt][3] == -INFINITY) ? 0.0f : __expf(s[nt][3] - mn1);
            rs0 += p0 + p1; rs1 += p2 + p3;
            Ps[rloc * ATT_PAD + c]           = p0;
            Ps[rloc * ATT_PAD + c + 1]       = p1;
            Ps[(rloc + 8) * ATT_PAD + c]     = p2;
            Ps[(rloc + 8) * ATT_PAD + c + 1] = p3;
        }
        rs0 += __shfl_xor_sync(0xffffffffu, rs0, 1);
        rs0 += __shfl_xor_sync(0xffffffffu, rs0, 2);
        rs1 += __shfl_xor_sync(0xffffffffu, rs1, 1);
        rs1 += __shfl_xor_sync(0xffffffffu, rs1, 2);
        l0 = l0 * c0 + rs0; l1 = l1 * c1 + rs1;
        m0 = mn0; m1 = mn1;
        #pragma unroll
        for (int nt = 0; nt < 8; nt++) {
            o[nt][0] *= c0; o[nt][1] *= c0;
            o[nt][2] *= c1; o[nt][3] *= c1;
        }
        __syncwarp();

        // ---- O += P @ V ----
        #pragma unroll
        for (int ks = 0; ks < 8; ks++) {
            int kk = ks * 8 + tg;
            uint32_t a[4] = {
                __float_as_uint(Ps[rloc * ATT_PAD + kk]),
                __float_as_uint(Ps[(rloc + 8) * ATT_PAD + kk]),
                __float_as_uint(Ps[rloc * ATT_PAD + kk + 4]),
                __float_as_uint(Ps[(rloc + 8) * ATT_PAD + kk + 4]) };
            #pragma unroll
            for (int nt = 0; nt < 8; nt++) {
                int n = nt * 8 + g;
                uint32_t b0 = __float_as_uint(Vt[n * ATT_PAD + kk]);
                uint32_t b1 = __float_as_uint(Vt[n * ATT_PAD + kk + 4]);
                mma_tf32(o[nt], a, b0, b1);
            }
        }
        __syncthreads();
    }

    float inv0 = (l0 > 0.0f) ? (1.0f / l0) : 0.0f;
    float inv1 = (l1 > 0.0f) ? (1.0f / l1) : 0.0f;
    float* Op = O + ((size_t)(b * SEQ + qt * 128 + rloc)) * D_MODEL + h * D_HEAD;
    #pragma unroll
    for (int nt = 0; nt < 8; nt++) {
        int c = nt * 8 + tg * 2;
        Op[c]     = f2tf32f(o[nt][0] * inv0);
        Op[c + 1] = f2tf32f(o[nt][1] * inv0);
        Op[(size_t)8 * D_MODEL + c]     = f2tf32f(o[nt][2] * inv1);
        Op[(size_t)8 * D_MODEL + c + 1] = f2tf32f(o[nt][3] * inv1);
    }
}

// ===========================================================================
// Launch
// ===========================================================================
extern "C" void kernel_launch(void* const* d_in, const int* in_sizes, int n_in,
                              void* d_out, int out_size) {
    const float* x     = (const float*)d_in[0];
    const int*   mask  = (const int*)  d_in[1];
    const float* wq    = (const float*)d_in[2];
    const float* bq    = (const float*)d_in[3];
    const float* wk    = (const float*)d_in[4];
    const float* bk    = (const float*)d_in[5];
    const float* wv    = (const float*)d_in[6];
    const float* bv    = (const float*)d_in[7];
    const float* wo    = (const float*)d_in[8];
    const float* bo    = (const float*)d_in[9];
    const float* ln1g  = (const float*)d_in[10];
    const float* ln1b  = (const float*)d_in[11];
    const float* ln2g  = (const float*)d_in[12];
    const float* ln2b  = (const float*)d_in[13];
    const float* w1    = (const float*)d_in[14];
    const float* b1    = (const float*)d_in[15];
    const float* w2    = (const float*)d_in[16];
    const float* b2    = (const float*)d_in[17];
    float* out = (float*)d_out;

    float *h, *qkv, *ctx, *x1, *ff;
    float *wqkvT, *woT, *w1T, *w2T, *bqkv;
    cudaGetSymbolAddress((void**)&h,     g_h);
    cudaGetSymbolAddress((void**)&qkv,   g_qkv);
    cudaGetSymbolAddress((void**)&ctx,   g_ctx);
    cudaGetSymbolAddress((void**)&x1,    g_x1);
    cudaGetSymbolAddress((void**)&ff,    g_ff);
    cudaGetSymbolAddress((void**)&wqkvT, g_wqkvT);
    cudaGetSymbolAddress((void**)&woT,   g_woT);
    cudaGetSymbolAddress((void**)&w1T,   g_w1T);
    cudaGetSymbolAddress((void**)&w2T,   g_w2T);
    cudaGetSymbolAddress((void**)&bqkv,  g_bqkv);

    cudaFuncSetAttribute(mmagemm<false, false, false>,
        cudaFuncAttributeMaxDynamicSharedMemorySize, GM_SMEM_B);
    cudaFuncSetAttribute(mmagemm<true, false, true>,
        cudaFuncAttributeMaxDynamicSharedMemorySize, GM_SMEM_B);
    cudaFuncSetAttribute(mmagemm<false, true, false>,
        cudaFuncAttributeMaxDynamicSharedMemorySize, GM_SMEM_B);
    cudaFuncSetAttribute(attn_mma,
        cudaFuncAttributeMaxDynamicSharedMemorySize, ATT_SMEM_B);

    dim3 tblk(32, 8);
    transpose_k<<<dim3(32, 32), tblk>>>(wq, wqkvT,                         D_MODEL, D_MODEL);
    transpose_k<<<dim3(32, 32), tblk>>>(wk, wqkvT + D_MODEL * D_MODEL,     D_MODEL, D_MODEL);
    transpose_k<<<dim3(32, 32), tblk>>>(wv, wqkvT + 2 * D_MODEL * D_MODEL, D_MODEL, D_MODEL);
    transpose_k<<<dim3(32, 32), tblk>>>(wo, woT, D_MODEL, D_MODEL);
    transpose_k<<<dim3(FF_DIM / 32, 32), tblk>>>(w1, w1T, D_MODEL, FF_DIM);
    transpose_k<<<dim3(32, FF_DIM / 32), tblk>>>(w2, w2T, FF_DIM, D_MODEL);
    concat_bias<<<QKV_LD / 256, 256>>>(bq, bk, bv, bqkv);

    // LN1
    ln_kernel<<<ROWS, 256>>>(x, ln1g, ln1b, h);
    // fused QKV projection
    mmagemm<false, false, false><<<dim3(QKV_LD / 128, ROWS / 128), 256, GM_SMEM_B>>>(
        h, wqkvT, bqkv, nullptr, qkv, ROWS, QKV_LD, D_MODEL);
    // attention (mma tf32)
    attn_mma<<<dim3(SEQ / 128, N_HEADS, BATCH), 256, ATT_SMEM_B>>>(qkv, mask, ctx);
    // output projection + residual
    mmagemm<false, true, false><<<dim3(D_MODEL / 128, ROWS / 128), 256, GM_SMEM_B>>>(
        ctx, woT, bo, x, x1, ROWS, D_MODEL, D_MODEL);
    // LN2
    ln_kernel<<<ROWS, 256>>>(x1, ln2g, ln2b, h);
    // FF1 (relu + tf32 round)
    mmagemm<true, false, true><<<dim3(FF_DIM / 128, ROWS / 128), 256, GM_SMEM_B>>>(
        h, w1T, b1, nullptr, ff, ROWS, FF_DIM, D_MODEL);
    // FF2 + residual -> out
    mmagemm<false, true, false><<<dim3(D_MODEL / 128, ROWS / 128), 256, GM_SMEM_B>>>(
        ff, w2T, b2, x1, out, ROWS, D_MODEL, FF_DIM);
}